// round 1
// baseline (speedup 1.0000x reference)
#include <cuda_runtime.h>
#include <cuda_bf16.h>
#include <math.h>

// ---------------------------------------------------------------------------
// NerfHash fused kernel: hash-grid encode + SH3 + feature MLP + RGB MLP.
// One thread per point. All MLP weights staged in dynamic shared memory.
// Inputs (metadata order):
//  0 samples_3d [N,3]  1 samples_dirs [N,3]  2 hash_table [24, 2^19, 2]
//  3 fw0[48,64] 4 fb0[64] 5 fw1[64,64] 6 fb1[64] 7 fw2[64,64] 8 fb2[64]
//  9 fw3[64,65] 10 fb3[65] 11 rw0[73,64] 12 rb0[64] 13 rw1[64,64] 14 rb1[64]
// 15 rw2[64,3] 16 rb2[3] 17 iter_nr (unused)
// Output: rgb [N,3] flattened, then density [N] -> out_size = 4N floats.
// ---------------------------------------------------------------------------

#define LVLS 24
#define TSZ  (1u << 19)
#define P1   2654435761u
#define P2   805459861u

struct ResArr { float r[LVLS]; };
struct WPtrs  { const float* w[14]; };

// shared-memory float offsets (16B aligned regions)
#define OFF_FW0 0
#define OFF_FB0 3072
#define OFF_FW1 3136
#define OFF_FB1 7232
#define OFF_FW2 7296
#define OFF_FB2 11392
#define OFF_FW3 11456
#define OFF_FB3 15616
#define OFF_RW0 15684
#define OFF_RB0 20356
#define OFF_RW1 20420
#define OFF_RB1 24516
#define OFF_RW2 24580
#define OFF_RB2 24772
#define SMEM_FLOATS 24776
#define SMEM_BYTES  (SMEM_FLOATS * 4)

__device__ __forceinline__ float gelu_exact(float x) {
    return 0.5f * x * (1.0f + erff(x * 0.70710678118654752440f));
}

__device__ __forceinline__ float softplus_f(float x) {
    return fmaxf(x, 0.0f) + log1pf(expf(-fabsf(x)));
}

__device__ __forceinline__ float sigmoid_f(float x) {
    return 1.0f / (1.0f + expf(-x));
}

template<int IN, int OUT, bool ACT>
__device__ __forceinline__ void dense(const float* __restrict__ in,
                                      float* __restrict__ out,
                                      const float* __restrict__ W,
                                      const float* __restrict__ B) {
#pragma unroll
    for (int j0 = 0; j0 < OUT; j0 += 32) {
        float acc[32];
#pragma unroll
        for (int jj = 0; jj < 32; jj++)
            if (j0 + jj < OUT) acc[jj] = B[j0 + jj];
#pragma unroll 4
        for (int i = 0; i < IN; i++) {
            float v = in[i];
#pragma unroll
            for (int jj = 0; jj < 32; jj++)
                if (j0 + jj < OUT)
                    acc[jj] = fmaf(v, W[i * OUT + j0 + jj], acc[jj]);
        }
#pragma unroll
        for (int jj = 0; jj < 32; jj++)
            if (j0 + jj < OUT)
                out[j0 + jj] = ACT ? gelu_exact(acc[jj]) : acc[jj];
    }
}

__global__ void __launch_bounds__(256)
nerf_fused_kernel(const float* __restrict__ pts,
                  const float* __restrict__ dirs,
                  const float* __restrict__ table,
                  WPtrs prm, ResArr res,
                  float* __restrict__ out, int n)
{
    extern __shared__ float s[];

    // ---- stage all weights into shared ----
    {
        const int sz[14]  = {3072,64,4096,64,4096,64,4160,65,4672,64,4096,64,192,3};
        const int off[14] = {OFF_FW0,OFF_FB0,OFF_FW1,OFF_FB1,OFF_FW2,OFF_FB2,
                             OFF_FW3,OFF_FB3,OFF_RW0,OFF_RB0,OFF_RW1,OFF_RB1,
                             OFF_RW2,OFF_RB2};
#pragma unroll 1
        for (int a = 0; a < 14; a++) {
            const float* src = prm.w[a];
            for (int k = threadIdx.x; k < sz[a]; k += blockDim.x)
                s[off[a] + k] = src[k];
        }
    }
    __syncthreads();

    int i = blockIdx.x * blockDim.x + threadIdx.x;
    if (i >= n) return;

    float px = pts[i * 3 + 0];
    float py = pts[i * 3 + 1];
    float pz = pts[i * 3 + 2];
    // x = (p+1)*0.5 (match reference op order/rounding)
    float x0 = (px + 1.0f) * 0.5f;
    float y0 = (py + 1.0f) * 0.5f;
    float z0 = (pz + 1.0f) * 0.5f;

    // ---- hash-grid encoding: enc[48] ----
    float enc[48];
#pragma unroll 1
    for (int l = 0; l < LVLS; l++) {
        float rl = res.r[l];
        float posx = x0 * rl, posy = y0 * rl, posz = z0 * rl;
        float fx = floorf(posx), fy = floorf(posy), fz = floorf(posz);
        float wx = posx - fx, wy = posy - fy, wz = posz - fz;
        unsigned ux = (unsigned)fx, uy = (unsigned)fy, uz = (unsigned)fz;

        unsigned hx0 = ux;                 // *PRIMES[0]==1
        unsigned hx1 = ux + 1u;
        unsigned hy0 = uy * P1;
        unsigned hy1 = (uy + 1u) * P1;
        unsigned hz0 = uz * P2;
        unsigned hz1 = (uz + 1u) * P2;

        const float2* base = (const float2*)(table) + (size_t)l * TSZ;

        float wX[2] = {1.0f - wx, wx};
        float wY[2] = {1.0f - wy, wy};
        float wZ[2] = {1.0f - wz, wz};
        unsigned hX[2] = {hx0, hx1};
        unsigned hY[2] = {hy0, hy1};
        unsigned hZ[2] = {hz0, hz1};

        // issue all 8 gathers up front for MLP
        float2 f[8];
        float  wt[8];
#pragma unroll
        for (int c = 0; c < 8; c++) {
            int bx = (c >> 2) & 1, by = (c >> 1) & 1, bz = c & 1;
            unsigned idx = (hX[bx] ^ hY[by] ^ hZ[bz]) & (TSZ - 1u);
            f[c]  = __ldg(base + idx);
            wt[c] = wX[bx] * wY[by] * wZ[bz];
        }
        float a0 = 0.0f, a1 = 0.0f;
#pragma unroll
        for (int c = 0; c < 8; c++) {
            a0 = fmaf(f[c].x, wt[c], a0);
            a1 = fmaf(f[c].y, wt[c], a1);
        }
        enc[2 * l + 0] = a0;
        enc[2 * l + 1] = a1;
    }

    // ---- SH3 direction encoding ----
    float dx = dirs[i * 3 + 0];
    float dy = dirs[i * 3 + 1];
    float dz = dirs[i * 3 + 2];
    float sh[9];
    sh[0] = 0.28209479177387814f;
    sh[1] = -0.48860251190291987f * dy;
    sh[2] =  0.48860251190291987f * dz;
    sh[3] = -0.48860251190291987f * dx;
    sh[4] =  1.0925484305920792f  * dx * dy;
    sh[5] = -1.0925484305920792f  * dy * dz;
    sh[6] =  0.31539156525252005f * (3.0f * dz * dz - 1.0f);
    sh[7] = -1.0925484305920792f  * dx * dz;
    sh[8] =  0.5462742152960396f  * (dx * dx - dy * dy);

    // ---- feature MLP ----
    float h0[64], h1[64];
    dense<48, 64, true>(enc, h0, s + OFF_FW0, s + OFF_FB0);
    dense<64, 64, true>(h0,  h1, s + OFF_FW1, s + OFF_FB1);
    dense<64, 64, true>(h1,  h0, s + OFF_FW2, s + OFF_FB2);
    float fad[65];
    dense<64, 65, false>(h0, fad, s + OFF_FW3, s + OFF_FB3);

    float density = softplus_f(fad[0]);

    // ---- RGB MLP input: gelu(fad[1:65]) ++ sh[9] ----
    float xin[73];
#pragma unroll
    for (int j = 0; j < 64; j++) xin[j] = gelu_exact(fad[1 + j]);
#pragma unroll
    for (int j = 0; j < 9; j++)  xin[64 + j] = sh[j];

    dense<73, 64, true>(xin, h1, s + OFF_RW0, s + OFF_RB0);
    dense<64, 64, true>(h1,  h0, s + OFF_RW1, s + OFF_RB1);
    float rgb[3];
    dense<64, 3, false>(h0, rgb, s + OFF_RW2, s + OFF_RB2);

    out[i * 3 + 0] = sigmoid_f(rgb[0]);
    out[i * 3 + 1] = sigmoid_f(rgb[1]);
    out[i * 3 + 2] = sigmoid_f(rgb[2]);
    out[(size_t)3 * n + i] = density;
}

extern "C" void kernel_launch(void* const* d_in, const int* in_sizes, int n_in,
                              void* d_out, int out_size)
{
    const float* pts   = (const float*)d_in[0];
    const float* dirs  = (const float*)d_in[1];
    const float* table = (const float*)d_in[2];

    WPtrs prm;
    for (int a = 0; a < 14; a++) prm.w[a] = (const float*)d_in[3 + a];

    int n = in_sizes[0] / 3;

    // RES[l] = floor(16 * b^l), b = exp((ln 2048 - ln 16)/23), double math
    ResArr res;
    double b = exp((log(2048.0) - log(16.0)) / 23.0);
    double v = 16.0;
    for (int l = 0; l < LVLS; l++) {
        res.r[l] = (float)floor(16.0 * pow(b, (double)l));
        (void)v;
    }

    cudaFuncSetAttribute(nerf_fused_kernel,
                         cudaFuncAttributeMaxDynamicSharedMemorySize, SMEM_BYTES);

    int threads = 256;
    int blocks = (n + threads - 1) / threads;
    nerf_fused_kernel<<<blocks, threads, SMEM_BYTES>>>(
        pts, dirs, table, prm, res, (float*)d_out, n);
}